// round 2
// baseline (speedup 1.0000x reference)
#include <cuda_runtime.h>

#define CH 4
#define HDIM 1025
#define WDIM 1024
#define NTOT (CH*HDIM*WDIM)
#define SEG 64
#define BS 128

// scratch (allocation-free rule: __device__ globals)
__device__ __align__(16) float g_ST[NTOT];      // S transposed: (4, 1024, 1025)
__device__ __align__(16) float g_harmT[NTOT];   // harmonic median, transposed layout
__device__ __align__(16) float g_perc[NTOT];    // percussive median, natural layout

__device__ __forceinline__ float finf() { return __int_as_float(0x7f800000); }

__device__ __forceinline__ void cas(float& a, float& b) {
    float lo = fminf(a, b);
    float hi = fmaxf(a, b);
    a = lo; b = hi;
}

// Batcher odd-even mergesort for N a power of two, fully unrolled (registers)
template<int N>
__device__ __forceinline__ void sortN(float* a) {
#pragma unroll
    for (int p = 1; p < N; p <<= 1)
#pragma unroll
        for (int k = p; k >= 1; k >>= 1)
#pragma unroll
            for (int j = k & (p - 1); j + k < N; j += 2 * k)
#pragma unroll
                for (int i = 0; i < k; ++i)
                    if (i + j + k < N)
                        if (((i + j) / (2 * p)) == ((i + j + k) / (2 * p)))
                            cas(a[i + j], a[i + j + k]);
}

// ---------------- transpose: S (4,1025,1024) -> ST (4,1024,1025) ----------------
__global__ void __launch_bounds__(256) transpose_kernel(const float* __restrict__ S) {
    __shared__ float tile[32][33];
    int ch = blockIdx.z;
    int h0 = blockIdx.y * 32;
    int w0 = blockIdx.x * 32;
    int tx = threadIdx.x, ty = threadIdx.y;   // (32, 8)
    const float* Sp = S + (size_t)ch * HDIM * WDIM;
#pragma unroll
    for (int i = 0; i < 4; ++i) {
        int h = h0 + ty + i * 8;
        if (h < HDIM) tile[ty + i * 8][tx] = Sp[(size_t)h * WDIM + (w0 + tx)];
    }
    __syncthreads();
    float* STp = g_ST + (size_t)ch * WDIM * HDIM;
#pragma unroll
    for (int i = 0; i < 4; ++i) {
        int w = w0 + ty + i * 8;
        int h = h0 + tx;
        if (h < HDIM) STp[(size_t)w * HDIM + h] = tile[tx][ty + i * 8];
    }
}

// ---------------- column median-31 (zero padded), sliding sorted window ----------------
// A viewed as (4, R, Cc); median along R for every column. One thread handles one
// (column, SEG-row segment). Window v[0..30] sorted ascending; v[31] scratch/INF.
template<int R, int Cc>
__global__ void __launch_bounds__(BS) colmed_kernel(const float* __restrict__ A,
                                                    float* __restrict__ Out,
                                                    int nJobs) {
    int job = blockIdx.x * BS + threadIdx.x;
    if (job >= nJobs) return;
    const int nCols = 4 * Cc;
    int seg = job / nCols;
    int colIdx = job - seg * nCols;
    int ch = colIdx / Cc;
    int c = colIdx - ch * Cc;
    const float* in = A + (size_t)ch * R * Cc + c;
    float* out = Out + (size_t)ch * R * Cc + c;
    int r0 = seg * SEG;
    int r1 = min(r0 + SEG, R);

    float v[32];
    // prologue: window(r0) = padded positions r0-15 .. r0+15, sorted
#pragma unroll
    for (int i = 0; i < 31; ++i) {
        int p = r0 - 15 + i;
        float x = 0.f;
        if (p >= 0 && p < R) x = in[(size_t)p * Cc];
        v[i] = x;
    }
    v[31] = finf();
    sortN<32>(v);

    for (int r = r0; r < r1; ++r) {
        out[(size_t)r * Cc] = v[15];
        // slide window(r) -> window(r+1)
        int ro = r - 15, ri = r + 16;
        float xo = 0.f, xi = 0.f;
        if (ro >= 0) xo = in[(size_t)ro * Cc];   // ro < R always
        if (ri < R)  xi = in[(size_t)ri * Cc];
        // delete xo (present by construction): shift-left from its slot, INF fills top
#pragma unroll
        for (int i = 0; i < 30; ++i) v[i] = (v[i] < xo) ? v[i] : v[i + 1];
        v[30] = (v[30] < xo) ? v[30] : finf();
        // insert xi: min/max cascade; the INF sentinel pops out the top
        float t = xi;
#pragma unroll
        for (int i = 0; i < 31; ++i) {
            float lo = fminf(v[i], t);
            t = fmaxf(v[i], t);
            v[i] = lo;
        }
    }
}

// ---------------- softmask + outputs (de-transposes harm via shared tile) ----------------
// mask_h = h^2/(h^2+p^2); mask_p = p^2/(h^2+p^2); both 0.5 when h=p=0.
__global__ void __launch_bounds__(256) mask_kernel(const float* __restrict__ S,
                                                   float* __restrict__ outA,
                                                   float* __restrict__ outB) {
    __shared__ float tile[32][33];
    int ch = blockIdx.z;
    int h0 = blockIdx.y * 32;
    int w0 = blockIdx.x * 32;
    int tx = threadIdx.x, ty = threadIdx.y;   // (32, 8)
    const float* HT = g_harmT + (size_t)ch * WDIM * HDIM;
#pragma unroll
    for (int i = 0; i < 4; ++i) {
        int wl = ty + i * 8;
        int h = h0 + tx;
        if (h < HDIM) tile[wl][tx] = HT[(size_t)(w0 + wl) * HDIM + h];
    }
    __syncthreads();
    size_t chOff = (size_t)ch * HDIM * WDIM;
#pragma unroll
    for (int i = 0; i < 4; ++i) {
        int h = h0 + ty + i * 8;
        if (h < HDIM) {
            int w = w0 + tx;
            size_t idx = chOff + (size_t)h * WDIM + w;
            float hv = tile[tx][ty + i * 8];
            float pv = g_perc[idx];
            float s = S[idx];
            float hh = hv * hv, pp = pv * pv;
            float d = hh + pp;
            float oa, ob;
            if (d > 0.f) {
                float rcp = 1.0f / d;
                oa = s * hh * rcp;
                ob = s * pp * rcp;
            } else {
                oa = 0.5f * s;
                ob = 0.5f * s;
            }
            outA[idx] = oa;
            outB[idx] = ob;
        }
    }
}

extern "C" void kernel_launch(void* const* d_in, const int* in_sizes, int n_in,
                              void* d_out, int out_size) {
    const float* S = (const float*)d_in[0];
    float* out = (float*)d_out;

    float* ST;    cudaGetSymbolAddress((void**)&ST, g_ST);
    float* harmT; cudaGetSymbolAddress((void**)&harmT, g_harmT);
    float* perc;  cudaGetSymbolAddress((void**)&perc, g_perc);

    // 1) transpose S into ST
    transpose_kernel<<<dim3(WDIM / 32, (HDIM + 31) / 32, CH), dim3(32, 8)>>>(S);

    // 2) harmonic: median along original W == column median on ST (R=1024, Cc=1025)
    {
        const int nSegs = (WDIM + SEG - 1) / SEG;        // 16
        const int nJobs = nSegs * 4 * HDIM;              // 16 * 4100
        colmed_kernel<WDIM, HDIM><<<(nJobs + BS - 1) / BS, BS>>>(ST, harmT, nJobs);
    }

    // 3) percussive: median along H, natural layout (R=1025, Cc=1024)
    {
        const int nSegs = (HDIM + SEG - 1) / SEG;        // 17
        const int nJobs = nSegs * 4 * WDIM;              // 17 * 4096
        colmed_kernel<HDIM, WDIM><<<(nJobs + BS - 1) / BS, BS>>>(S, perc, nJobs);
    }

    // 4) masks + both outputs
    mask_kernel<<<dim3(WDIM / 32, (HDIM + 31) / 32, CH), dim3(32, 8)>>>(S, out, out + NTOT);
}